// round 13
// baseline (speedup 1.0000x reference)
#include <cuda_runtime.h>

#define Hh 192
#define Ww 192
#define HW (192*192)
#define CIN 64
#define COUT 64
#define NB 2
#define MT 128
#define NPIX (NB*HW)

// Scratch (no allocations allowed in kernel_launch)
__device__ float4 g_params[NPIX];          // per-pixel (sin, cos, r, wr)
__device__ float  g_wT[9*CIN*COUT];        // w_main transposed to [k][c][o]

// ---------------------------------------------------------------------------
// Kernel 1: per-pixel parameter convs (4 output channels over 64 in, 3x3 SAME)
// One block = one (b, h) row, 192 threads = w.
// ---------------------------------------------------------------------------
__global__ __launch_bounds__(192) void param_kernel(
    const float* __restrict__ x,
    const float* __restrict__ w_rot,   const float* __restrict__ b_rot,
    const float* __restrict__ w_str,   const float* __restrict__ b_str,
    const float* __restrict__ w_whole, const float* __restrict__ b_whole)
{
    __shared__ float4 ws[CIN * 9];  // (rot0, rot1, str, whole) per (c,k)
    for (int i = threadIdx.x; i < CIN * 9; i += 192) {
        ws[i] = make_float4(w_rot[i], w_rot[CIN*9 + i], w_str[i], w_whole[i]);
    }
    __syncthreads();

    const int bh = blockIdx.x;
    const int b  = bh / Hh;
    const int h  = bh - b * Hh;
    const int w  = threadIdx.x;
    const float* xb = x + (size_t)b * CIN * HW;

    float a0 = 0.f, a1 = 0.f, a2 = 0.f, a3 = 0.f;
    for (int c = 0; c < CIN; c++) {
        const float* xc = xb + c * HW;
        #pragma unroll
        for (int kh = 0; kh < 3; kh++) {
            const int y = h + kh - 1;
            const bool yv = ((unsigned)y < (unsigned)Hh);
            const float* xr = xc + y * Ww;
            #pragma unroll
            for (int kw = 0; kw < 3; kw++) {
                const int xw = w + kw - 1;
                const float v = (yv && (unsigned)xw < (unsigned)Ww) ? xr[xw] : 0.f;
                const float4 wv = ws[c * 9 + kh * 3 + kw];
                a0 = fmaf(v, wv.x, a0);
                a1 = fmaf(v, wv.y, a1);
                a2 = fmaf(v, wv.z, a2);
                a3 = fmaf(v, wv.w, a3);
            }
        }
    }

    float s  = a0 + b_rot[0];
    float co = a1 + b_rot[1];
    const float nrm = sqrtf(s * s + co * co + 1e-6f);
    s  /= nrm;
    co /= nrm;
    const float r  = tanhf(a2 + b_str[0]) * 1.25f + 1.75f;   // A_S=1.25, B_S=1.75
    const float wr = 1.f + fmaxf(a3 + b_whole[0], 0.f);

    g_params[bh * Ww + w] = make_float4(s, co, r, wr);
}

// ---------------------------------------------------------------------------
// Kernel 2: transpose w_main[o][c][k] -> g_wT[k][c][o]
// ---------------------------------------------------------------------------
__global__ void transpose_w(const float* __restrict__ wm)
{
    const int i = blockIdx.x * 256 + threadIdx.x;   // over 64*64*9 = 36864
    if (i < COUT * CIN * 9) {
        const int o   = i / (CIN * 9);
        const int rem = i - o * (CIN * 9);
        const int c   = rem / 9;
        const int k   = rem - c * 9;
        g_wT[(k * CIN + c) * COUT + o] = wm[i];
    }
}

// ---------------------------------------------------------------------------
// Kernel 3: deformable sampling + implicit GEMM.
// Block = 128 consecutive pixels x 64 outputs; 128 threads, 8x8 frags, FFMA2.
// ---------------------------------------------------------------------------
__global__ __launch_bounds__(128) void deform_kernel(
    const float* __restrict__ x, float* __restrict__ out)
{
    __shared__ float As[CIN][MT];      // [c][pixel]   32 KB
    __shared__ float Bs[CIN][COUT];    // [c][o]       16 KB

    const int tid = threadIdx.x;
    const int m0  = blockIdx.x * MT;
    const int pix = m0 + tid;
    const int b   = pix / HW;
    const int hw  = pix - b * HW;
    const int h   = hw / Ww;
    const int w   = hw - h * Ww;

    const float4 prm = g_params[pix];
    const float sinn = prm.x, cosn = prm.y, rr = prm.z, wrv = prm.w;
    const float* xb = x + (size_t)b * CIN * HW;

    const int tx = tid & 15;   // pixel group:  pixels tx*8 .. tx*8+7
    const int ty = tid >> 4;   // output group: outputs ty*8 .. ty*8+7

    unsigned long long acc[8][4];      // 8 pixels x 4 f32x2 pairs (8 outputs)
    #pragma unroll
    for (int i = 0; i < 8; i++)
        #pragma unroll
        for (int j = 0; j < 4; j++)
            acc[i][j] = 0ull;

    #pragma unroll 1
    for (int k = 0; k < 9; k++) {
        // --- stage B tile: wT[k][c][o] -> Bs ---
        {
            const float4* src  = (const float4*)(g_wT + k * CIN * COUT);
            float4*       dstB = (float4*)&Bs[0][0];
            #pragma unroll
            for (int i = 0; i < 8; i++)
                dstB[i * 128 + tid] = src[i * 128 + tid];
        }

        // --- per-(pixel, tap) sampling coordinates ---
        const int   kdiv = k / 3;
        const float di = (float)(kdiv - 1);
        const float dj = (float)(k - kdiv * 3 - 1);
        const float bd0 = di * rr * wrv;
        const float bd1 = dj * wrv;
        const float py = (float)h + cosn * bd0 + sinn * bd1;
        const float px = (float)w - sinn * bd0 + cosn * bd1;
        const float y0f = floorf(py), x0f = floorf(px);
        const float fy = py - y0f, fx = px - x0f;
        const int y0 = (int)y0f, x0 = (int)x0f;
        const int y1 = y0 + 1,   x1 = x0 + 1;
        float w00 = (1.f - fy) * (1.f - fx);
        float w01 = (1.f - fy) * fx;
        float w10 = fy * (1.f - fx);
        float w11 = fy * fx;
        const bool y0v = ((unsigned)y0 < (unsigned)Hh);
        const bool y1v = ((unsigned)y1 < (unsigned)Hh);
        const bool x0v = ((unsigned)x0 < (unsigned)Ww);
        const bool x1v = ((unsigned)x1 < (unsigned)Ww);
        if (!(y0v && x0v)) w00 = 0.f;
        if (!(y0v && x1v)) w01 = 0.f;
        if (!(y1v && x0v)) w10 = 0.f;
        if (!(y1v && x1v)) w11 = 0.f;
        const int y0c = min(max(y0, 0), Hh - 1);
        const int y1c = min(max(y1, 0), Hh - 1);
        const int x0c = min(max(x0, 0), Ww - 1);
        const int x1c = min(max(x1, 0), Ww - 1);
        const float* p00 = xb + y0c * Ww + x0c;
        const float* p01 = xb + y0c * Ww + x1c;
        const float* p10 = xb + y1c * Ww + x0c;
        const float* p11 = xb + y1c * Ww + x1c;

        // --- build sampled A tile: As[c][tid] ---
        #pragma unroll 8
        for (int c = 0; c < CIN; c++) {
            float s = fmaf(w00, p00[c * HW],
                      fmaf(w01, p01[c * HW],
                      fmaf(w10, p10[c * HW],
                           w11 * p11[c * HW])));
            As[c][tid] = s;
        }
        __syncthreads();

        // --- 8x8 fragment GEMM over this tap's 64 channels (FFMA2) ---
        #pragma unroll 4
        for (int c = 0; c < CIN; c++) {
            const float4 a0 = *(const float4*)&As[c][tx * 8];
            const float4 a1 = *(const float4*)&As[c][tx * 8 + 4];
            const ulonglong2 bp0 = *(const ulonglong2*)&Bs[c][ty * 8];
            const ulonglong2 bp1 = *(const ulonglong2*)&Bs[c][ty * 8 + 4];
            const unsigned long long bb0 = bp0.x, bb1 = bp0.y;
            const unsigned long long bb2 = bp1.x, bb3 = bp1.y;
            const float av[8] = {a0.x, a0.y, a0.z, a0.w, a1.x, a1.y, a1.z, a1.w};
            #pragma unroll
            for (int i = 0; i < 8; i++) {
                unsigned long long ai;
                asm("mov.b64 %0, {%1, %1};" : "=l"(ai) : "f"(av[i]));
                asm("fma.rn.f32x2 %0, %1, %2, %0;" : "+l"(acc[i][0]) : "l"(ai), "l"(bb0));
                asm("fma.rn.f32x2 %0, %1, %2, %0;" : "+l"(acc[i][1]) : "l"(ai), "l"(bb1));
                asm("fma.rn.f32x2 %0, %1, %2, %0;" : "+l"(acc[i][2]) : "l"(ai), "l"(bb2));
                asm("fma.rn.f32x2 %0, %1, %2, %0;" : "+l"(acc[i][3]) : "l"(ai), "l"(bb3));
            }
        }
        __syncthreads();
    }

    // --- restage through smem for coalesced stores (reuse As: 8192 floats) ---
    float* Asf = &As[0][0];
    #pragma unroll
    for (int i = 0; i < 8; i++) {
        #pragma unroll
        for (int j = 0; j < 4; j++) {
            float lo, hi;
            asm("mov.b64 {%0, %1}, %2;" : "=f"(lo), "=f"(hi) : "l"(acc[i][j]));
            Asf[(ty * 8 + 2 * j)     * MT + tx * 8 + i] = lo;
            Asf[(ty * 8 + 2 * j + 1) * MT + tx * 8 + i] = hi;
        }
    }
    __syncthreads();

    // m0 is a multiple of 128 and HW = 36864 = 288*128, so a block never
    // straddles the batch boundary: 128 consecutive pixels are contiguous in
    // each output-channel plane.
    const int b0  = m0 / HW;
    const int hw0 = m0 - b0 * HW;
    const float4* s4 = (const float4*)Asf;
    float4* o4 = (float4*)out;
    #pragma unroll
    for (int jj = 0; jj < 16; jj++) {
        const int idx = jj * 128 + tid;          // 0..2047 float4s
        const int o   = idx >> 5;                // 32 float4 per output channel
        const int p4  = idx & 31;
        o4[((size_t)(b0 * COUT + o)) * (HW / 4) + (hw0 >> 2) + p4] = s4[idx];
    }
}

// ---------------------------------------------------------------------------
// Launch
// ---------------------------------------------------------------------------
extern "C" void kernel_launch(void* const* d_in, const int* in_sizes, int n_in,
                              void* d_out, int out_size)
{
    const float* x       = (const float*)d_in[0];
    const float* w_main  = (const float*)d_in[1];
    const float* w_rot   = (const float*)d_in[2];
    const float* b_rot   = (const float*)d_in[3];
    const float* w_str   = (const float*)d_in[4];
    const float* b_str   = (const float*)d_in[5];
    const float* w_whole = (const float*)d_in[6];
    const float* b_whole = (const float*)d_in[7];
    float* out = (float*)d_out;

    param_kernel<<<NB * Hh, 192>>>(x, w_rot, b_rot, w_str, b_str, w_whole, b_whole);
    transpose_w<<<(COUT * CIN * 9 + 255) / 256, 256>>>(w_main);
    deform_kernel<<<NPIX / MT, 128>>>(x, out);
}

// round 14
// speedup vs baseline: 1.0990x; 1.0990x over previous
#include <cuda_runtime.h>

#define Hh 192
#define Ww 192
#define HW (192*192)
#define CIN 64
#define COUT 64
#define NB 2
#define MT 128
#define NPIX (NB*HW)
#define DSMEM ((2*CIN*MT + 2*CIN*COUT)*4)   // 96 KB dynamic smem for deform

// Scratch (no allocations allowed)
__device__ float4 g_params[NPIX];          // per-pixel (sin, cos, r, wr)
__device__ float  g_wT[9*CIN*COUT];        // w_main transposed to [k][c][o]

// ---------------------------------------------------------------------------
// Kernel 1: per-pixel parameter convs, smem row-staged, channel double-buffer.
// One block = one (b, h) row, 192 threads = w.
// ---------------------------------------------------------------------------
__global__ __launch_bounds__(192) void param_kernel(
    const float* __restrict__ x,
    const float* __restrict__ w_rot,   const float* __restrict__ b_rot,
    const float* __restrict__ w_str,   const float* __restrict__ b_str,
    const float* __restrict__ w_whole, const float* __restrict__ b_whole)
{
    __shared__ float4 ws[CIN * 9];        // (rot0, rot1, str, whole) per (c,k)
    __shared__ float  sx[2][3][200];      // double-buffered 3-row halo strip

    for (int i = threadIdx.x; i < CIN * 9; i += 192)
        ws[i] = make_float4(w_rot[i], w_rot[CIN*9 + i], w_str[i], w_whole[i]);

    const int bh = blockIdx.x;
    const int b  = bh / Hh;
    const int h  = bh - b * Hh;
    const int w  = threadIdx.x;
    const float* xb = x + (size_t)b * CIN * HW;

    int  yy[3]; bool yv[3];
    #pragma unroll
    for (int r = 0; r < 3; r++) { yy[r] = h + r - 1; yv[r] = ((unsigned)yy[r] < (unsigned)Hh); }

    auto load_chan = [&](int c, int buf) {
        const float* xc = xb + c * HW;
        #pragma unroll
        for (int r = 0; r < 3; r++) {
            const float* xr = xc + yy[r] * Ww;
            for (int i = threadIdx.x; i < Ww + 2; i += 192) {
                const int j = i - 1;
                sx[buf][r][i] = (yv[r] && (unsigned)j < (unsigned)Ww) ? xr[j] : 0.f;
            }
        }
    };

    float a0 = 0.f, a1 = 0.f, a2 = 0.f, a3 = 0.f;
    load_chan(0, 0);
    __syncthreads();

    for (int c = 0; c < CIN; c++) {
        if (c + 1 < CIN) load_chan(c + 1, (c + 1) & 1);
        const int buf = c & 1;
        const float4* wc = ws + c * 9;
        #pragma unroll
        for (int kh = 0; kh < 3; kh++)
            #pragma unroll
            for (int kw = 0; kw < 3; kw++) {
                const float  v  = sx[buf][kh][w + kw];
                const float4 wv = wc[kh * 3 + kw];
                a0 = fmaf(v, wv.x, a0);
                a1 = fmaf(v, wv.y, a1);
                a2 = fmaf(v, wv.z, a2);
                a3 = fmaf(v, wv.w, a3);
            }
        __syncthreads();
    }

    float s  = a0 + b_rot[0];
    float co = a1 + b_rot[1];
    const float nrm = sqrtf(s * s + co * co + 1e-6f);
    s  /= nrm;
    co /= nrm;
    const float r  = tanhf(a2 + b_str[0]) * 1.25f + 1.75f;   // A_S=1.25, B_S=1.75
    const float wr = 1.f + fmaxf(a3 + b_whole[0], 0.f);

    g_params[bh * Ww + w] = make_float4(s, co, r, wr);
}

// ---------------------------------------------------------------------------
// Kernel 2: transpose w_main[o][c][k] -> g_wT[k][c][o]
// ---------------------------------------------------------------------------
__global__ void transpose_w(const float* __restrict__ wm)
{
    const int i = blockIdx.x * 256 + threadIdx.x;   // over 64*64*9 = 36864
    if (i < COUT * CIN * 9) {
        const int o   = i / (CIN * 9);
        const int rem = i - o * (CIN * 9);
        const int c   = rem / 9;
        const int k   = rem - c * 9;
        g_wT[(k * CIN + c) * COUT + o] = wm[i];
    }
}

// ---------------------------------------------------------------------------
// Kernel 3: warp-specialized deformable sampling + implicit GEMM.
// 256 threads: tid<128 = producers (sample tap k+1 into buf^1),
//              tid>=128 = consumers (FFMA2 8x8-frag GEMM on buf).
// Double-buffered As/Bs in 96 KB dynamic smem; one barrier per tap.
// ---------------------------------------------------------------------------
__global__ __launch_bounds__(256, 2) void deform_kernel(
    const float* __restrict__ x, float* __restrict__ out)
{
    extern __shared__ float smem[];
    float* AsBase = smem;                       // [2][CIN][MT]  64 KB
    float* BsBase = smem + 2 * CIN * MT;        // [2][CIN][COUT] 32 KB

    const int  tid      = threadIdx.x;
    const int  m0       = blockIdx.x * MT;
    const bool producer = (tid < MT);

    // --- producer per-pixel state ---
    float sinn = 0.f, cosn = 0.f, rr = 0.f, wrv = 0.f;
    const float* xb = x;
    int h = 0, w = 0;
    if (producer) {
        const int pix = m0 + tid;
        const int b   = pix / HW;
        const int hw  = pix - b * HW;
        h = hw / Ww;
        w = hw - h * Ww;
        const float4 prm = g_params[pix];
        sinn = prm.x; cosn = prm.y; rr = prm.z; wrv = prm.w;
        xb = x + (size_t)b * CIN * HW;
    }

    auto fillB = [&](int k, int buf) {
        const float4* src = (const float4*)(g_wT + k * CIN * COUT);
        float4*       dst = (float4*)(BsBase + buf * CIN * COUT);
        #pragma unroll
        for (int i = 0; i < 8; i++)
            dst[i * 128 + tid] = src[i * 128 + tid];
    };

    auto fillA = [&](int k, int buf) {
        const int   kdiv = k / 3;
        const float di = (float)(kdiv - 1);
        const float dj = (float)(k - kdiv * 3 - 1);
        const float bd0 = di * rr * wrv;
        const float bd1 = dj * wrv;
        const float py = (float)h + cosn * bd0 + sinn * bd1;
        const float px = (float)w - sinn * bd0 + cosn * bd1;
        const float y0f = floorf(py), x0f = floorf(px);
        const float fy = py - y0f, fx = px - x0f;
        const int y0 = (int)y0f, x0 = (int)x0f;
        const int y1 = y0 + 1,   x1 = x0 + 1;
        float w00 = (1.f - fy) * (1.f - fx);
        float w01 = (1.f - fy) * fx;
        float w10 = fy * (1.f - fx);
        float w11 = fy * fx;
        const bool y0v = ((unsigned)y0 < (unsigned)Hh);
        const bool y1v = ((unsigned)y1 < (unsigned)Hh);
        const bool x0v = ((unsigned)x0 < (unsigned)Ww);
        const bool x1v = ((unsigned)x1 < (unsigned)Ww);
        if (!(y0v && x0v)) w00 = 0.f;
        if (!(y0v && x1v)) w01 = 0.f;
        if (!(y1v && x0v)) w10 = 0.f;
        if (!(y1v && x1v)) w11 = 0.f;
        const int y0c = min(max(y0, 0), Hh - 1);
        const int y1c = min(max(y1, 0), Hh - 1);
        const int x0c = min(max(x0, 0), Ww - 1);
        const int x1c = min(max(x1, 0), Ww - 1);
        const float* p00 = xb + y0c * Ww + x0c;
        const float* p01 = xb + y0c * Ww + x1c;
        const float* p10 = xb + y1c * Ww + x0c;
        const float* p11 = xb + y1c * Ww + x1c;
        float* dstA = AsBase + buf * CIN * MT;
        #pragma unroll 8
        for (int c = 0; c < CIN; c++) {
            const float s = fmaf(w00, p00[c * HW],
                            fmaf(w01, p01[c * HW],
                            fmaf(w10, p10[c * HW],
                                 w11 * p11[c * HW])));
            dstA[c * MT + tid] = s;
        }
    };

    // --- consumer state ---
    const int ctid = tid - MT;
    const int tx   = ctid & 15;   // pixels tx*8 .. tx*8+7
    const int ty   = ctid >> 4;   // outputs ty*8 .. ty*8+7
    unsigned long long acc[8][4];
    #pragma unroll
    for (int i = 0; i < 8; i++)
        #pragma unroll
        for (int j = 0; j < 4; j++)
            acc[i][j] = 0ull;

    // --- prologue: producers stage tap 0 ---
    if (producer) { fillB(0, 0); fillA(0, 0); }
    __syncthreads();

    #pragma unroll 1
    for (int k = 0; k < 9; k++) {
        const int cur = k & 1;
        if (producer) {
            if (k < 8) { fillB(k + 1, cur ^ 1); fillA(k + 1, cur ^ 1); }
        } else {
            const float* A = AsBase + cur * CIN * MT;
            const float* B = BsBase + cur * CIN * COUT;
            #pragma unroll 4
            for (int c = 0; c < CIN; c++) {
                const float4 a0 = *(const float4*)(A + c * MT + tx * 8);
                const float4 a1 = *(const float4*)(A + c * MT + tx * 8 + 4);
                const ulonglong2 bp0 = *(const ulonglong2*)(B + c * COUT + ty * 8);
                const ulonglong2 bp1 = *(const ulonglong2*)(B + c * COUT + ty * 8 + 4);
                const unsigned long long bb0 = bp0.x, bb1 = bp0.y;
                const unsigned long long bb2 = bp1.x, bb3 = bp1.y;
                const float av[8] = {a0.x, a0.y, a0.z, a0.w, a1.x, a1.y, a1.z, a1.w};
                #pragma unroll
                for (int i = 0; i < 8; i++) {
                    unsigned long long ai;
                    asm("mov.b64 %0, {%1, %1};" : "=l"(ai) : "f"(av[i]));
                    asm("fma.rn.f32x2 %0, %1, %2, %0;" : "+l"(acc[i][0]) : "l"(ai), "l"(bb0));
                    asm("fma.rn.f32x2 %0, %1, %2, %0;" : "+l"(acc[i][1]) : "l"(ai), "l"(bb1));
                    asm("fma.rn.f32x2 %0, %1, %2, %0;" : "+l"(acc[i][2]) : "l"(ai), "l"(bb2));
                    asm("fma.rn.f32x2 %0, %1, %2, %0;" : "+l"(acc[i][3]) : "l"(ai), "l"(bb3));
                }
            }
        }
        __syncthreads();
    }

    // --- epilogue: consumers restage accs into smem for coalesced stores ---
    if (!producer) {
        #pragma unroll
        for (int i = 0; i < 8; i++) {
            #pragma unroll
            for (int j = 0; j < 4; j++) {
                float lo, hi;
                asm("mov.b64 {%0, %1}, %2;" : "=f"(lo), "=f"(hi) : "l"(acc[i][j]));
                AsBase[(ty * 8 + 2 * j)     * MT + tx * 8 + i] = lo;
                AsBase[(ty * 8 + 2 * j + 1) * MT + tx * 8 + i] = hi;
            }
        }
    }
    __syncthreads();

    // HW = 36864 = 288*128 so a block never straddles the batch boundary.
    const int b0  = m0 / HW;
    const int hw0 = m0 - b0 * HW;
    const float4* s4 = (const float4*)AsBase;
    float4* o4 = (float4*)out;
    #pragma unroll
    for (int jj = 0; jj < 8; jj++) {
        const int idx = jj * 256 + tid;          // 0..2047 float4s
        const int o   = idx >> 5;                // 32 float4 per output channel
        const int p4  = idx & 31;
        o4[((size_t)(b0 * COUT + o)) * (HW / 4) + (hw0 >> 2) + p4] = s4[idx];
    }
}

// ---------------------------------------------------------------------------
// Launch
// ---------------------------------------------------------------------------
extern "C" void kernel_launch(void* const* d_in, const int* in_sizes, int n_in,
                              void* d_out, int out_size)
{
    const float* x       = (const float*)d_in[0];
    const float* w_main  = (const float*)d_in[1];
    const float* w_rot   = (const float*)d_in[2];
    const float* b_rot   = (const float*)d_in[3];
    const float* w_str   = (const float*)d_in[4];
    const float* b_str   = (const float*)d_in[5];
    const float* w_whole = (const float*)d_in[6];
    const float* b_whole = (const float*)d_in[7];
    float* out = (float*)d_out;

    cudaFuncSetAttribute(deform_kernel,
                         cudaFuncAttributeMaxDynamicSharedMemorySize, DSMEM);

    param_kernel<<<NB * Hh, 192>>>(x, w_rot, b_rot, w_str, b_str, w_whole, b_whole);
    transpose_w<<<(COUT * CIN * 9 + 255) / 256, 256>>>(w_main);
    deform_kernel<<<NPIX / MT, 256, DSMEM>>>(x, out);
}